// round 12
// baseline (speedup 1.0000x reference)
#include <cuda_runtime.h>
#include <cuda_fp16.h>
#include <cstdint>

// Problem constants
#define FH 100
#define FW 100
#define NC 1024
#define NK 7
#define NT 81
#define NTP 88           // padded targets (11 n8-tiles; rows 81..87 zero)
#define NR 1024
#define NBINS 49
#define KTOT (NBINS*NC)  // 50176

// Fused kernel tiling: grid (NBINS, 32). CTA: 1 bin, 32 regions, 8 chunks of 128 ch.
#define MTILE 32
#define NCH 8

// SMEM layout (rows are 256B data + 16B pad = 272B, ldmatrix conflict-free)
#define ROWB 272
#define AB_SZ    (MTILE*ROWB)            // 8704, x2 stages
#define BB_SZ    (NTP*ROWB)              // 23936, x2 stages
#define BB_OFF   (2*AB_SZ)               // 17408
#define MP_OFF   (BB_OFF + 2*BB_SZ)      // 65280: meta uint2 [32][16]
#define SM_TOTAL (MP_OFF + MTILE*16*8)   // 69376  (x3 CTAs = 208KB <= 228KB)

// Scratch (device globals; no allocation)
__device__ __half g_xt[FH*FW*NC];                       // (HW, C) fp16
__device__ __half g_wp2[(size_t)NTP*KTOT];              // (Tpad, bin*C) fp16, K-major
__device__ float  g_partial[(size_t)NR*NBINS*NTP];      // (r, bin, t) f32
__device__ float  g_bias[96];

// ---------------- helpers ----------------
__device__ __forceinline__ void cpa16s(uint32_t s, const void* g) {
    asm volatile("cp.async.cg.shared.global [%0], [%1], 16;" :: "r"(s), "l"(g));
}
__device__ __forceinline__ void cpa_commit() { asm volatile("cp.async.commit_group;"); }
template<int N> __device__ __forceinline__ void cpa_wait() {
    asm volatile("cp.async.wait_group %0;" :: "n"(N));
}
__device__ __forceinline__ void mma16816(float* d, uint32_t a0, uint32_t a1,
                                         uint32_t a2, uint32_t a3,
                                         uint32_t b0, uint32_t b1) {
    asm volatile(
        "mma.sync.aligned.m16n8k16.row.col.f32.f16.f16.f32 "
        "{%0,%1,%2,%3}, {%4,%5,%6,%7}, {%8,%9}, {%0,%1,%2,%3};"
        : "+f"(d[0]), "+f"(d[1]), "+f"(d[2]), "+f"(d[3])
        : "r"(a0), "r"(a1), "r"(a2), "r"(a3), "r"(b0), "r"(b1));
}
__device__ __forceinline__ void ldm_x4(uint32_t& r0, uint32_t& r1, uint32_t& r2,
                                       uint32_t& r3, uint32_t addr) {
    asm volatile("ldmatrix.sync.aligned.m8n8.x4.shared.b16 {%0,%1,%2,%3}, [%4];"
        : "=r"(r0), "=r"(r1), "=r"(r2), "=r"(r3) : "r"(addr));
}
__device__ __forceinline__ void ldm_x2(uint32_t& r0, uint32_t& r1, uint32_t addr) {
    asm volatile("ldmatrix.sync.aligned.m8n8.x2.shared.b16 {%0,%1}, [%2];"
        : "=r"(r0), "=r"(r1) : "r"(addr));
}
__device__ __forceinline__ float2 h2f2(unsigned v) {
    __half2 h = *reinterpret_cast<__half2*>(&v);
    return __half22float2(h);
}
// packed f32x2 FMA: acc += half2(hv)-as-float2 * wv2  (bit-identical to 2 scalar FMAs)
__device__ __forceinline__ void ffma2h(unsigned long long& acc, unsigned hv,
                                       unsigned long long wv2) {
    float2 c = h2f2(hv);
    unsigned long long cp;
    asm("mov.b64 %0, {%1,%2};" : "=l"(cp) : "f"(c.x), "f"(c.y));
    asm("fma.rn.f32x2 %0, %1, %2, %0;" : "+l"(acc) : "l"(cp), "l"(wv2));
}
__device__ __forceinline__ unsigned cvth2(unsigned long long a) {
    float lo, hi;
    asm("mov.b64 {%0,%1}, %2;" : "=f"(lo), "=f"(hi) : "l"(a));
    __half2 h = __floats2half2_rn(lo, hi);
    return *reinterpret_cast<unsigned*>(&h);
}

// ---------------- Kernel 1: fused prep (transpose + weight permute + bias)
#define TPB 313   // ceil(10000/32)
__global__ void k_prep(const float* __restrict__ x,
                       const float* __restrict__ conv_w,
                       const float* __restrict__ conv_b) {
    int bid = blockIdx.x;
    int tid = threadIdx.x;
    if (bid < TPB*16) {
        __shared__ float tile[64][33];
        int p0 = (bid % TPB) * 32;
        int c0 = (bid / TPB) * 64;
        int tx = tid & 31, ty = tid >> 5;
        #pragma unroll
        for (int j = 0; j < 8; j++) {
            int c = c0 + ty + j*8;
            int p = p0 + tx;
            float v = 0.0f;
            if (p < FH*FW) v = x[c*(FH*FW) + p];
            tile[ty + j*8][tx] = v;
        }
        __syncthreads();
        int pl = tid >> 3, cg = tid & 7;
        int p = p0 + pl;
        if (p < FH*FW) {
            uint4 o;
            __half2 h;
            h = __floats2half2_rn(tile[cg*8+0][pl], tile[cg*8+1][pl]); o.x = *(unsigned*)&h;
            h = __floats2half2_rn(tile[cg*8+2][pl], tile[cg*8+3][pl]); o.y = *(unsigned*)&h;
            h = __floats2half2_rn(tile[cg*8+4][pl], tile[cg*8+5][pl]); o.z = *(unsigned*)&h;
            h = __floats2half2_rn(tile[cg*8+6][pl], tile[cg*8+7][pl]); o.w = *(unsigned*)&h;
            *(uint4*)&g_xt[(size_t)p*NC + c0 + cg*8] = o;
        }
    } else if (bid < TPB*16 + 276) {
        int idx = (bid - TPB*16)*256 + tid;
        if (idx >= NTP*NBINS*16) return;
        int t = idx / (NBINS*16);
        int rem = idx - t*(NBINS*16);
        int bin = rem >> 4;
        int c0 = (rem & 15) * 64;
        __half* dst = g_wp2 + (size_t)t*KTOT + bin*NC + c0;
        if (t < NT) {
            const float* src = conv_w + ((size_t)t*NBINS + bin)*NC + c0;
            #pragma unroll
            for (int j = 0; j < 64; j += 8) {
                float4 f0 = *(const float4*)(src + j);
                float4 f1 = *(const float4*)(src + j + 4);
                __half2 h0 = __floats2half2_rn(f0.x, f0.y);
                __half2 h1 = __floats2half2_rn(f0.z, f0.w);
                __half2 h2 = __floats2half2_rn(f1.x, f1.y);
                __half2 h3 = __floats2half2_rn(f1.z, f1.w);
                uint4 o;
                o.x = *reinterpret_cast<unsigned*>(&h0);
                o.y = *reinterpret_cast<unsigned*>(&h1);
                o.z = *reinterpret_cast<unsigned*>(&h2);
                o.w = *reinterpret_cast<unsigned*>(&h3);
                *reinterpret_cast<uint4*>(dst + j) = o;
            }
        } else {
            uint4 z = {0u, 0u, 0u, 0u};
            #pragma unroll
            for (int j = 0; j < 64; j += 8) *reinterpret_cast<uint4*>(dst + j) = z;
        }
    } else {
        if (tid < 96) {
            float bm = 0.0f;
            if (tid < NT) {
                #pragma unroll 7
                for (int b = 0; b < NBINS; b++) bm += conv_b[tid*NBINS + b];
                bm *= (1.0f/49.0f);
            }
            g_bias[tid] = bm;
        }
    }
}

// ---------------- Kernel 2: FUSED PSROIAlign pooling + HMMA GEMM
// grid (NBINS, 32), 256 threads, 3 CTAs/SM. CTA: bin b, regions [mt*32, +32).
__global__ void __launch_bounds__(256, 3) k_poolmma(const float* __restrict__ regions) {
    extern __shared__ char dsm[];
    char* Ab = dsm;
    uint2* smeta = (uint2*)(dsm + MP_OFF);

    uint32_t su;
    asm("{ .reg .u64 t; cvta.to.shared.u64 t, %1; cvt.u32.u64 %0, t; }" : "=r"(su) : "l"(dsm));

    int tid = threadIdx.x;
    int w = tid >> 5, l = tid & 31;
    int b = blockIdx.x, mt = blockIdx.y;
    int m0 = mt * MTILE;
    int u = b / NK, v = b - u*NK;

    // ---- meta: 16 (pixel byte-offset, weight) pairs per region ----
    if (tid < MTILE) {
        float4 reg = reinterpret_cast<const float4*>(regions)[m0 + tid];
        float top  = (reg.x - reg.z*0.5f)*(float)FH;
        float left = (reg.y - reg.w*0.5f)*(float)FW;
        float bh = reg.z*((float)FH/(float)NK);
        float bw = reg.w*((float)FW/(float)NK);
        int yi[2][2]; float wy[2][2];
        int xi[2][2]; float wx[2][2];
        #pragma unroll
        for (int s = 0; s < 2; s++) {
            float ys = top + ((float)u + (s ? 0.75f : 0.25f))*bh;
            ys = fminf(fmaxf(ys, 0.0f), 99.0f);
            float yf = floorf(ys);
            int y0 = (int)yf;
            yi[s][0] = y0; yi[s][1] = min(y0 + 1, 99);
            wy[s][1] = ys - yf; wy[s][0] = 1.0f - wy[s][1];
            float xs = left + ((float)v + (s ? 0.75f : 0.25f))*bw;
            xs = fminf(fmaxf(xs, 0.0f), 99.0f);
            float xf = floorf(xs);
            int x0 = (int)xf;
            xi[s][0] = x0; xi[s][1] = min(x0 + 1, 99);
            wx[s][1] = xs - xf; wx[s][0] = 1.0f - wx[s][1];
        }
        #pragma unroll
        for (int sy = 0; sy < 2; sy++)
        #pragma unroll
        for (int sx = 0; sx < 2; sx++)
        #pragma unroll
        for (int cy = 0; cy < 2; cy++)
        #pragma unroll
        for (int cx = 0; cx < 2; cx++) {
            int i = sy*8 + sx*4 + cy*2 + cx;
            uint32_t pix = (uint32_t)(yi[sy][cy]*FW + xi[sx][cx]);
            uint2 m;
            m.x = pix * (NC*2);            // byte offset into g_xt
            m.y = __float_as_uint(wy[sy][cy]*wx[sx][cx]);
            smeta[tid*16 + i] = m;
        }
    }

    // ---- B prologue: chunk 0 into stage 0 ----
    const char* gB = (const char*)g_wp2 + (size_t)b*NC*2;
    // per-thread B-copy slots: row = ch>>4, c16 = ch&15 for ch = i*256+tid
    {
        #pragma unroll
        for (int i = 0; i < 6; i++) {
            int ch = i*256 + tid;
            if (ch < NTP*16) {
                int row = ch >> 4, c16 = ch & 15;
                cpa16s(su + BB_OFF + row*ROWB + c16*16,
                       gB + (size_t)row*(KTOT*2) + c16*16);
            }
        }
        cpa_commit();
    }
    __syncthreads();   // meta visible

    int rb = w & 1;           // 16-row block
    int ng = w >> 1;          // n-tile group: tiles [ng*3, +3) (last group: 2)
    int t0 = ng*3;
    int tcnt = (ng == 3) ? 2 : 3;

    float acc[3][4];
    #pragma unroll
    for (int t = 0; t < 3; t++)
        #pragma unroll
        for (int i = 0; i < 4; i++) acc[t][i] = 0.0f;

    int r8 = tid >> 3;        // region 0..31
    int lane8 = tid & 7;      // 16B lane within each 128B half

    const char* xb = (const char*)g_xt + lane8*16;   // advanced 256B per chunk
    uint32_t aSts = su + r8*ROWB + lane8*16;          // + sA*AB_SZ at use

    // ldmatrix per-lane address offsets (bytes)
    int lm = l >> 3;
    int lr = l & 7;
    uint32_t aOff  = su + (uint32_t)((rb*16 + (lm & 1)*8 + lr)*ROWB + (lm >> 1)*16);
    uint32_t bOff4 = su + BB_OFF + (uint32_t)(((lm >> 1)*8 + lr)*ROWB + (lm & 1)*16
                                              + t0*8*ROWB);
    uint32_t bOff2 = su + BB_OFF + (uint32_t)((l & 7)*ROWB + ((l >> 3) & 1)*16
                                              + (t0+2)*8*ROWB);
    const uint2* mp = smeta + r8*16;

    for (int kc = 0; kc < NCH; kc++) {
        uint32_t sAoff = (kc & 1) ? AB_SZ : 0;
        uint32_t sBoff = (kc & 1) ? BB_SZ : 0;

        // ---- gather: 32 regions, 8 lanes/region, 2x128B per sample ----
        {
            unsigned long long f[8];
            #pragma unroll
            for (int j = 0; j < 8; j++) f[j] = 0ull;
            #pragma unroll
            for (int i = 0; i < 16; i++) {
                uint2 m = mp[i];
                float wv = __uint_as_float(m.y);
                unsigned long long wv2;
                asm("mov.b64 %0, {%1,%1};" : "=l"(wv2) : "f"(wv));
                uint4 d0 = *(const uint4*)(xb + m.x);
                uint4 d1 = *(const uint4*)(xb + m.x + 128);
                ffma2h(f[0], d0.x, wv2);
                ffma2h(f[1], d0.y, wv2);
                ffma2h(f[2], d0.z, wv2);
                ffma2h(f[3], d0.w, wv2);
                ffma2h(f[4], d1.x, wv2);
                ffma2h(f[5], d1.y, wv2);
                ffma2h(f[6], d1.z, wv2);
                ffma2h(f[7], d1.w, wv2);
            }
            uint4 o0, o1;
            o0.x = cvth2(f[0]); o0.y = cvth2(f[1]);
            o0.z = cvth2(f[2]); o0.w = cvth2(f[3]);
            o1.x = cvth2(f[4]); o1.y = cvth2(f[5]);
            o1.z = cvth2(f[6]); o1.w = cvth2(f[7]);
            uint32_t as = aSts + sAoff;
            *(uint4*)(dsm + (as - su)) = o0;
            *(uint4*)(dsm + (as - su) + 128) = o1;
        }
        xb += 256;

        cpa_wait<0>();      // B[kc] resident
        __syncthreads();    // + A stores visible; all warps past MMA[kc-1]

        // ---- MMA over this 128-K chunk ----
        uint32_t aBase = aOff + sAoff;
        #pragma unroll
        for (int q = 0; q < 8; q++) {
            uint32_t k0b = (uint32_t)(q*32);
            uint32_t a0, a1, a2, a3;
            ldm_x4(a0, a1, a2, a3, aBase + k0b);
            if (ng < 3) {
                uint32_t b00, b01, b10, b11, b20, b21;
                ldm_x4(b00, b01, b10, b11, bOff4 + sBoff + k0b);
                ldm_x2(b20, b21, bOff2 + sBoff + k0b);
                mma16816(acc[0], a0, a1, a2, a3, b00, b01);
                mma16816(acc[1], a0, a1, a2, a3, b10, b11);
                mma16816(acc[2], a0, a1, a2, a3, b20, b21);
            } else {
                uint32_t b00, b01, b10, b11;
                ldm_x4(b00, b01, b10, b11, bOff4 + sBoff + k0b);
                mma16816(acc[0], a0, a1, a2, a3, b00, b01);
                mma16816(acc[1], a0, a1, a2, a3, b10, b11);
            }
        }

        // ---- prefetch B[kc+1] into the other stage (safe: all warps past sync) ----
        if (kc + 1 < NCH) {
            uint32_t st = (kc & 1) ? 0 : BB_SZ;
            const char* gBk = gB + (size_t)(kc+1)*256;
            #pragma unroll
            for (int i = 0; i < 6; i++) {
                int ch = i*256 + tid;
                if (ch < NTP*16) {
                    int row = ch >> 4, c16 = ch & 15;
                    cpa16s(su + BB_OFF + st + row*ROWB + c16*16,
                           gBk + (size_t)row*(KTOT*2) + c16*16);
                }
            }
        }
        cpa_commit();
    }

    // ---- epilogue: write (r, bin, t) layout ----
    int mr = l >> 2;
    int kc2 = (l & 3) * 2;
    int r0 = m0 + rb*16 + mr;
    #pragma unroll
    for (int t = 0; t < 3; t++) {
        if (t < tcnt) {
            int c = (t0 + t)*8 + kc2;
            *(float2*)&g_partial[((size_t)r0*NBINS + b)*NTP + c] =
                make_float2(acc[t][0], acc[t][1]);
            *(float2*)&g_partial[((size_t)(r0+8)*NBINS + b)*NTP + c] =
                make_float2(acc[t][2], acc[t][3]);
        }
    }
}

// ---------------- Kernel 3: reduce bins (float4), apply 1/196 mean + bias
__global__ void k_reduce(float* __restrict__ out) {
    int tx = threadIdx.x;
    int r = blockIdx.x*8 + threadIdx.y;
    if (tx >= 22) return;
    const float4* po = (const float4*)(g_partial + (size_t)r*NBINS*NTP) + tx;
    float4 a = make_float4(0.f, 0.f, 0.f, 0.f);
    #pragma unroll
    for (int b = 0; b < NBINS; b++) {
        float4 v = po[b*(NTP/4)];
        a.x += v.x; a.y += v.y; a.z += v.z; a.w += v.w;
    }
    int t = tx*4;
    float s = 1.0f/196.0f;
    float vs[4] = {a.x*s, a.y*s, a.z*s, a.w*s};
    #pragma unroll
    for (int i = 0; i < 4; i++) {
        int ti = t + i;
        if (ti < NT) out[r*NT + ti] = vs[i] + g_bias[ti];
    }
}

extern "C" void kernel_launch(void* const* d_in, const int* in_sizes, int n_in,
                              void* d_out, int out_size) {
    const float* x       = (const float*)d_in[0];   // (1024, 100, 100)
    const float* regions = (const float*)d_in[1];   // (1024, 4)
    const float* conv_w  = (const float*)d_in[2];   // (3969, 1024)
    const float* conv_b  = (const float*)d_in[3];   // (3969,)
    float* out = (float*)d_out;                     // (1024, 81)

    cudaFuncSetAttribute(k_poolmma, cudaFuncAttributeMaxDynamicSharedMemorySize, SM_TOTAL);

    k_prep<<<TPB*16 + 276 + 1, 256>>>(x, conv_w, conv_b);
    k_poolmma<<<dim3(NBINS, NR/MTILE), 256, SM_TOTAL>>>(regions);
    k_reduce<<<NR/8, dim3(32, 8)>>>(out);
}

// round 14
// speedup vs baseline: 1.0311x; 1.0311x over previous
#include <cuda_runtime.h>
#include <cuda_fp16.h>
#include <cstdint>

// Problem constants
#define FH 100
#define FW 100
#define NC 1024
#define NK 7
#define NT 81
#define NTP 88           // padded targets (11 n8-tiles; rows 81..87 zero)
#define NR 1024
#define NBINS 49
#define KTOT (NBINS*NC)  // 50176

// Fused kernel tiling: grid (NBINS, 16). CTA: 1 bin, 64 regions, 8 chunks of 128 ch.
#define MTILE 64
#define NCH 8

// SMEM layout (rows are 256B data + 16B pad = 272B, ldmatrix conflict-free)
#define ROWB 272
#define AB_SZ    (MTILE*ROWB)            // 17408, x2 stages
#define BB_SZ    (NTP*ROWB)              // 23936, x3 stages
#define BB_OFF   (2*AB_SZ)               // 34816
#define MP_OFF   (BB_OFF + 3*BB_SZ)      // 106624: meta uint2 [64][16]
#define SM_TOTAL (MP_OFF + MTILE*16*8)   // 114816

// Scratch (device globals; no allocation)
__device__ __half g_xt[FH*FW*NC];                       // (HW, C) fp16
__device__ __half g_wp2[(size_t)NTP*KTOT];              // (Tpad, bin*C) fp16, K-major
__device__ float  g_partial[(size_t)NR*NBINS*NTP];      // (r, bin, t) f32
__device__ float  g_bias[96];

// ---------------- helpers ----------------
__device__ __forceinline__ void cpa16(void* s, const void* g) {
    uint32_t a;
    asm("{ .reg .u64 t; cvta.to.shared.u64 t, %1; cvt.u32.u64 %0, t; }" : "=r"(a) : "l"(s));
    asm volatile("cp.async.cg.shared.global [%0], [%1], 16;" :: "r"(a), "l"(g));
}
__device__ __forceinline__ void cpa_commit() { asm volatile("cp.async.commit_group;"); }
template<int N> __device__ __forceinline__ void cpa_wait() {
    asm volatile("cp.async.wait_group %0;" :: "n"(N));
}
__device__ __forceinline__ void mma16816(float* d, uint32_t a0, uint32_t a1,
                                         uint32_t a2, uint32_t a3,
                                         uint32_t b0, uint32_t b1) {
    asm volatile(
        "mma.sync.aligned.m16n8k16.row.col.f32.f16.f16.f32 "
        "{%0,%1,%2,%3}, {%4,%5,%6,%7}, {%8,%9}, {%0,%1,%2,%3};"
        : "+f"(d[0]), "+f"(d[1]), "+f"(d[2]), "+f"(d[3])
        : "r"(a0), "r"(a1), "r"(a2), "r"(a3), "r"(b0), "r"(b1));
}
__device__ __forceinline__ void ldm_x4(uint32_t& r0, uint32_t& r1, uint32_t& r2,
                                       uint32_t& r3, uint32_t addr) {
    asm volatile("ldmatrix.sync.aligned.m8n8.x4.shared.b16 {%0,%1,%2,%3}, [%4];"
        : "=r"(r0), "=r"(r1), "=r"(r2), "=r"(r3) : "r"(addr));
}
__device__ __forceinline__ void ldm_x2(uint32_t& r0, uint32_t& r1, uint32_t addr) {
    asm volatile("ldmatrix.sync.aligned.m8n8.x2.shared.b16 {%0,%1}, [%2];"
        : "=r"(r0), "=r"(r1) : "r"(addr));
}
__device__ __forceinline__ float2 h2f2(unsigned v) {
    __half2 h = *reinterpret_cast<__half2*>(&v);
    return __half22float2(h);
}
// packed f32x2 FMA: acc += half2(hv)-as-float2 * wv2  (bit-identical to 2 scalar FMAs)
__device__ __forceinline__ void ffma2h(unsigned long long& acc, unsigned hv,
                                       unsigned long long wv2) {
    float2 c = h2f2(hv);
    unsigned long long cp;
    asm("mov.b64 %0, {%1,%2};" : "=l"(cp) : "f"(c.x), "f"(c.y));
    asm("fma.rn.f32x2 %0, %1, %2, %0;" : "+l"(acc) : "l"(cp), "l"(wv2));
}
__device__ __forceinline__ unsigned cvth2(unsigned long long a) {
    float lo, hi;
    asm("mov.b64 {%0,%1}, %2;" : "=f"(lo), "=f"(hi) : "l"(a));
    __half2 h = __floats2half2_rn(lo, hi);
    return *reinterpret_cast<unsigned*>(&h);
}

// ---------------- Kernel 1: fused prep (transpose + weight permute + bias)
// Transpose: 32p x 128c tiles, 16 LDGs in flight, XOR-swizzled smem.
#define TPB 313   // ceil(10000/32)
__global__ void k_prep(const float* __restrict__ x,
                       const float* __restrict__ conv_w,
                       const float* __restrict__ conv_b) {
    int bid = blockIdx.x;
    int tid = threadIdx.x;
    if (bid < TPB*8) {
        __shared__ float tile[128][33];
        int p0 = (bid % TPB) * 32;
        int c0 = (bid / TPB) * 128;
        int tx = tid & 31, ty = tid >> 5;   // ty 0..7
        int p = p0 + tx;
        #pragma unroll
        for (int j = 0; j < 16; j++) {
            int c = c0 + ty + j*8;           // rows ty+j*8 cover 0..127
            float v = 0.0f;
            if (p < FH*FW) v = x[c*(FH*FW) + p];
            tile[ty + j*8][tx ^ j] = v;      // swizzle col by (row>>3)=j
        }
        __syncthreads();
        #pragma unroll
        for (int i = 0; i < 2; i++) {
            int item = i*256 + tid;
            int pl = item >> 4;              // 0..31
            int cg = item & 15;              // 0..15 (8 ch each)
            int pw = p0 + pl;
            if (pw < FH*FW) {
                int sc = pl ^ cg;            // unswizzle: row>>3 = cg
                uint4 o;
                __half2 h;
                h = __floats2half2_rn(tile[cg*8+0][sc], tile[cg*8+1][sc]); o.x = *(unsigned*)&h;
                h = __floats2half2_rn(tile[cg*8+2][sc], tile[cg*8+3][sc]); o.y = *(unsigned*)&h;
                h = __floats2half2_rn(tile[cg*8+4][sc], tile[cg*8+5][sc]); o.z = *(unsigned*)&h;
                h = __floats2half2_rn(tile[cg*8+6][sc], tile[cg*8+7][sc]); o.w = *(unsigned*)&h;
                *(uint4*)&g_xt[(size_t)pw*NC + c0 + cg*8] = o;
            }
        }
    } else if (bid < TPB*8 + 276) {
        int idx = (bid - TPB*8)*256 + tid;
        if (idx >= NTP*NBINS*16) return;
        int t = idx / (NBINS*16);
        int rem = idx - t*(NBINS*16);
        int bin = rem >> 4;
        int c0 = (rem & 15) * 64;
        __half* dst = g_wp2 + (size_t)t*KTOT + bin*NC + c0;
        if (t < NT) {
            const float* src = conv_w + ((size_t)t*NBINS + bin)*NC + c0;
            #pragma unroll
            for (int j = 0; j < 64; j += 8) {
                float4 f0 = *(const float4*)(src + j);
                float4 f1 = *(const float4*)(src + j + 4);
                __half2 h0 = __floats2half2_rn(f0.x, f0.y);
                __half2 h1 = __floats2half2_rn(f0.z, f0.w);
                __half2 h2 = __floats2half2_rn(f1.x, f1.y);
                __half2 h3 = __floats2half2_rn(f1.z, f1.w);
                uint4 o;
                o.x = *reinterpret_cast<unsigned*>(&h0);
                o.y = *reinterpret_cast<unsigned*>(&h1);
                o.z = *reinterpret_cast<unsigned*>(&h2);
                o.w = *reinterpret_cast<unsigned*>(&h3);
                *reinterpret_cast<uint4*>(dst + j) = o;
            }
        } else {
            uint4 z = {0u, 0u, 0u, 0u};
            #pragma unroll
            for (int j = 0; j < 64; j += 8) *reinterpret_cast<uint4*>(dst + j) = z;
        }
    } else {
        if (tid < 96) {
            float bm = 0.0f;
            if (tid < NT) {
                #pragma unroll 7
                for (int b = 0; b < NBINS; b++) bm += conv_b[tid*NBINS + b];
                bm *= (1.0f/49.0f);
            }
            g_bias[tid] = bm;
        }
    }
}

// ---------------- Kernel 2: FUSED PSROIAlign pooling + HMMA GEMM
// grid (NBINS, 16), 256 threads, 2 CTAs/SM. CTA: bin b, regions [mt*64, +64).
// Warp map: rbg = w&1 (32 rows), ng = w>>1 (n-tile group of 3/3/3/2).
__global__ void __launch_bounds__(256, 2) k_poolmma(const float* __restrict__ regions) {
    extern __shared__ char dsm[];
    char* Ab = dsm;
    char* Bb = dsm + BB_OFF;
    uint2* smeta = (uint2*)(dsm + MP_OFF);

    uint32_t su;
    asm("{ .reg .u64 t; cvta.to.shared.u64 t, %1; cvt.u32.u64 %0, t; }" : "=r"(su) : "l"(dsm));

    int tid = threadIdx.x;
    int w = tid >> 5, l = tid & 31;
    int b = blockIdx.x, mt = blockIdx.y;
    int m0 = mt * MTILE;
    int u = b / NK, v = b - u*NK;

    // ---- meta: 16 (pixel byte-offset, weight) pairs per region ----
    if (tid < MTILE) {
        float4 reg = reinterpret_cast<const float4*>(regions)[m0 + tid];
        float top  = (reg.x - reg.z*0.5f)*(float)FH;
        float left = (reg.y - reg.w*0.5f)*(float)FW;
        float bh = reg.z*((float)FH/(float)NK);
        float bw = reg.w*((float)FW/(float)NK);
        int yi[2][2]; float wy[2][2];
        int xi[2][2]; float wx[2][2];
        #pragma unroll
        for (int s = 0; s < 2; s++) {
            float ys = top + ((float)u + (s ? 0.75f : 0.25f))*bh;
            ys = fminf(fmaxf(ys, 0.0f), 99.0f);
            float yf = floorf(ys);
            int y0 = (int)yf;
            yi[s][0] = y0; yi[s][1] = min(y0 + 1, 99);
            wy[s][1] = ys - yf; wy[s][0] = 1.0f - wy[s][1];
            float xs = left + ((float)v + (s ? 0.75f : 0.25f))*bw;
            xs = fminf(fmaxf(xs, 0.0f), 99.0f);
            float xf = floorf(xs);
            int x0 = (int)xf;
            xi[s][0] = x0; xi[s][1] = min(x0 + 1, 99);
            wx[s][1] = xs - xf; wx[s][0] = 1.0f - wx[s][1];
        }
        #pragma unroll
        for (int sy = 0; sy < 2; sy++)
        #pragma unroll
        for (int sx = 0; sx < 2; sx++)
        #pragma unroll
        for (int cy = 0; cy < 2; cy++)
        #pragma unroll
        for (int cx = 0; cx < 2; cx++) {
            int i = sy*8 + sx*4 + cy*2 + cx;
            uint32_t pix = (uint32_t)(yi[sy][cy]*FW + xi[sx][cx]);
            uint2 m;
            m.x = pix * (NC*2);            // byte offset into g_xt
            m.y = __float_as_uint(wy[sy][cy]*wx[sx][cx]);
            smeta[tid*16 + i] = m;
        }
    }

    // ---- B prologue: chunk 0 into stage 0 ----
    const char* gB = (const char*)g_wp2 + (size_t)b*NC*2;
    #pragma unroll
    for (int i = 0; i < 6; i++) {
        int ch = i*256 + tid;
        if (ch < NTP*16) {
            int row = ch >> 4, c16 = ch & 15;
            cpa16(Bb + row*ROWB + c16*16, gB + (size_t)row*(KTOT*2) + c16*16);
        }
    }
    cpa_commit();
    __syncthreads();   // meta visible

    int rbg = w & 1;          // 32-row group
    int ng = w >> 1;          // n-tile group: [ng*3, +3), last group 2
    int t0 = ng*3;
    int tcnt = (ng == 3) ? 2 : 3;

    float acc[2][3][4];
    #pragma unroll
    for (int h = 0; h < 2; h++)
        #pragma unroll
        for (int t = 0; t < 3; t++)
            #pragma unroll
            for (int i = 0; i < 4; i++) acc[h][t][i] = 0.0f;

    int r8 = tid >> 3;        // region group 0..31 (task adds +32)
    int lane8 = tid & 7;      // 16B lane within each 128B half

    const char* xbase = (const char*)g_xt + lane8*16;

    // ldmatrix per-lane address offsets (bytes)
    int lm = l >> 3;
    int lr = l & 7;
    uint32_t aOff0 = (uint32_t)((rbg*32 + (lm & 1)*8 + lr)*ROWB + (lm >> 1)*16);
    uint32_t aOff1 = aOff0 + 16*ROWB;
    uint32_t bOff4 = (uint32_t)(((lm >> 1)*8 + lr)*ROWB + (lm & 1)*16 + t0*8*ROWB);
    uint32_t bOff2 = (uint32_t)((l & 7)*ROWB + ((l >> 3) & 1)*16 + (t0+2)*8*ROWB);

    int bStage = 0;           // stage holding chunk kc
    for (int kc = 0; kc < NCH; kc++) {
        int sA = kc & 1;
        uint32_t kb = (uint32_t)kc * 256;

        // ---- gather: 2 tasks, 8 lanes/region, 2x128B per sample, f32x2 FMAs ----
        #pragma unroll
        for (int task = 0; task < 2; task++) {
            int rr = r8 + task*32;
            const uint2* mp = smeta + rr*16;
            unsigned long long f[8];
            #pragma unroll
            for (int j = 0; j < 8; j++) f[j] = 0ull;
            #pragma unroll
            for (int i = 0; i < 16; i++) {
                uint2 m = mp[i];
                uint32_t off = m.x + kb;
                float wv = __uint_as_float(m.y);
                unsigned long long wv2;
                asm("mov.b64 %0, {%1,%1};" : "=l"(wv2) : "f"(wv));
                uint4 d0 = *(const uint4*)(xbase + off);
                uint4 d1 = *(const uint4*)(xbase + off + 128);
                ffma2h(f[0], d0.x, wv2);
                ffma2h(f[1], d0.y, wv2);
                ffma2h(f[2], d0.z, wv2);
                ffma2h(f[3], d0.w, wv2);
                ffma2h(f[4], d1.x, wv2);
                ffma2h(f[5], d1.y, wv2);
                ffma2h(f[6], d1.z, wv2);
                ffma2h(f[7], d1.w, wv2);
            }
            uint4 o0, o1;
            o0.x = cvth2(f[0]); o0.y = cvth2(f[1]);
            o0.z = cvth2(f[2]); o0.w = cvth2(f[3]);
            o1.x = cvth2(f[4]); o1.y = cvth2(f[5]);
            o1.z = cvth2(f[6]); o1.w = cvth2(f[7]);
            char* arow = Ab + sA*AB_SZ + rr*ROWB + lane8*16;
            *(uint4*)(arow) = o0;
            *(uint4*)(arow + 128) = o1;
        }

        // ---- prefetch B[kc+1] into stage (kc+1)%3 ----
        if (kc + 1 < NCH) {
            int st = bStage + 1; if (st == 3) st = 0;
            #pragma unroll
            for (int i = 0; i < 6; i++) {
                int ch = i*256 + tid;
                if (ch < NTP*16) {
                    int row = ch >> 4, c16 = ch & 15;
                    cpa16(Bb + st*BB_SZ + row*ROWB + c16*16,
                          gB + (size_t)row*(KTOT*2) + (kc+1)*256 + c16*16);
                }
            }
        }
        cpa_commit();
        cpa_wait<1>();      // B[kc] complete (this thread's share)
        __syncthreads();    // all shares + A stores visible

        // ---- MMA over this 128-K chunk ----
        uint32_t aBase0 = su + sA*AB_SZ + aOff0;
        uint32_t aBase1 = su + sA*AB_SZ + aOff1;
        uint32_t bBase = su + BB_OFF + bStage*BB_SZ;
        #pragma unroll
        for (int q = 0; q < 8; q++) {
            uint32_t k0b = (uint32_t)(q*32);
            uint32_t aA0, aA1, aA2, aA3, aB0, aB1, aB2, aB3;
            ldm_x4(aA0, aA1, aA2, aA3, aBase0 + k0b);
            ldm_x4(aB0, aB1, aB2, aB3, aBase1 + k0b);
            if (ng < 3) {
                uint32_t b0, b1, b2, b3, b4, b5;
                ldm_x4(b0, b1, b2, b3, bBase + bOff4 + k0b);
                ldm_x2(b4, b5, bBase + bOff2 + k0b);
                mma16816(acc[0][0], aA0, aA1, aA2, aA3, b0, b1);
                mma16816(acc[0][1], aA0, aA1, aA2, aA3, b2, b3);
                mma16816(acc[0][2], aA0, aA1, aA2, aA3, b4, b5);
                mma16816(acc[1][0], aB0, aB1, aB2, aB3, b0, b1);
                mma16816(acc[1][1], aB0, aB1, aB2, aB3, b2, b3);
                mma16816(acc[1][2], aB0, aB1, aB2, aB3, b4, b5);
            } else {
                uint32_t b0, b1, b2, b3;
                ldm_x4(b0, b1, b2, b3, bBase + bOff4 + k0b);
                mma16816(acc[0][0], aA0, aA1, aA2, aA3, b0, b1);
                mma16816(acc[0][1], aA0, aA1, aA2, aA3, b2, b3);
                mma16816(acc[1][0], aB0, aB1, aB2, aB3, b0, b1);
                mma16816(acc[1][1], aB0, aB1, aB2, aB3, b2, b3);
            }
        }
        bStage++; if (bStage == 3) bStage = 0;
    }

    // ---- epilogue: write (r, bin, t) layout ----
    int mr = l >> 2;
    int kc2 = (l & 3) * 2;
    #pragma unroll
    for (int h = 0; h < 2; h++) {
        int r0 = m0 + rbg*32 + h*16 + mr;
        #pragma unroll
        for (int t = 0; t < 3; t++) {
            if (t < tcnt) {
                int c = (t0 + t)*8 + kc2;
                *(float2*)&g_partial[((size_t)r0*NBINS + b)*NTP + c] =
                    make_float2(acc[h][t][0], acc[h][t][1]);
                *(float2*)&g_partial[((size_t)(r0+8)*NBINS + b)*NTP + c] =
                    make_float2(acc[h][t][2], acc[h][t][3]);
            }
        }
    }
}

// ---------------- Kernel 3: reduce bins (float4), apply 1/196 mean + bias
__global__ void k_reduce(float* __restrict__ out) {
    int tx = threadIdx.x;
    int r = blockIdx.x*8 + threadIdx.y;
    if (tx >= 22) return;
    const float4* po = (const float4*)(g_partial + (size_t)r*NBINS*NTP) + tx;
    float4 a = make_float4(0.f, 0.f, 0.f, 0.f);
    #pragma unroll
    for (int b = 0; b < NBINS; b++) {
        float4 v = po[b*(NTP/4)];
        a.x += v.x; a.y += v.y; a.z += v.z; a.w += v.w;
    }
    int t = tx*4;
    float s = 1.0f/196.0f;
    float vs[4] = {a.x*s, a.y*s, a.z*s, a.w*s};
    #pragma unroll
    for (int i = 0; i < 4; i++) {
        int ti = t + i;
        if (ti < NT) out[r*NT + ti] = vs[i] + g_bias[ti];
    }
}

extern "C" void kernel_launch(void* const* d_in, const int* in_sizes, int n_in,
                              void* d_out, int out_size) {
    const float* x       = (const float*)d_in[0];   // (1024, 100, 100)
    const float* regions = (const float*)d_in[1];   // (1024, 4)
    const float* conv_w  = (const float*)d_in[2];   // (3969, 1024)
    const float* conv_b  = (const float*)d_in[3];   // (3969,)
    float* out = (float*)d_out;                     // (1024, 81)

    cudaFuncSetAttribute(k_poolmma, cudaFuncAttributeMaxDynamicSharedMemorySize, SM_TOTAL);

    k_prep<<<TPB*8 + 276 + 1, 256>>>(x, conv_w, conv_b);
    k_poolmma<<<dim3(NBINS, NR/MTILE), 256, SM_TOTAL>>>(regions);
    k_reduce<<<NR/8, dim3(32, 8)>>>(out);
}

// round 16
// speedup vs baseline: 1.0608x; 1.0288x over previous
#include <cuda_runtime.h>
#include <cuda_fp16.h>
#include <cstdint>

// Problem constants
#define FH 100
#define FW 100
#define NC 1024
#define NK 7
#define NT 81
#define NTP 88           // padded targets (11 n8-tiles; rows 81..87 zero)
#define NR 1024
#define NBINS 49
#define KTOT (NBINS*NC)  // 50176

// Fused kernel tiling: grid (NBINS, 16). CTA: 1 bin, 64 regions, 8 chunks of 128 ch.
#define MTILE 64
#define NCH 8

// SMEM layout (rows are 256B data + 16B pad = 272B, ldmatrix conflict-free)
#define ROWB 272
#define AB_SZ    (MTILE*ROWB)            // 17408, x2 stages
#define BB_SZ    (NTP*ROWB)              // 23936, x3 stages
#define BB_OFF   (2*AB_SZ)               // 34816
#define MP_OFF   (BB_OFF + 3*BB_SZ)      // 106624: meta uint2 [64][16]
#define SM_TOTAL (MP_OFF + MTILE*16*8)   // 114816

// Scratch (device globals; no allocation)
__device__ __half g_xt[FH*FW*NC];                       // (HW, C) fp16
__device__ __half g_wp2[(size_t)NTP*KTOT];              // (Tpad, bin*C) fp16, K-major
__device__ float  g_partial[(size_t)NR*NBINS*NTP];      // (r, bin, t) f32
__device__ float  g_bias[96];

// ---------------- helpers ----------------
__device__ __forceinline__ void cpa16(void* s, const void* g) {
    uint32_t a;
    asm("{ .reg .u64 t; cvta.to.shared.u64 t, %1; cvt.u32.u64 %0, t; }" : "=r"(a) : "l"(s));
    asm volatile("cp.async.cg.shared.global [%0], [%1], 16;" :: "r"(a), "l"(g));
}
__device__ __forceinline__ void cpa_commit() { asm volatile("cp.async.commit_group;"); }
template<int N> __device__ __forceinline__ void cpa_wait() {
    asm volatile("cp.async.wait_group %0;" :: "n"(N));
}
__device__ __forceinline__ void mma16816(float* d, uint32_t a0, uint32_t a1,
                                         uint32_t a2, uint32_t a3,
                                         uint32_t b0, uint32_t b1) {
    asm volatile(
        "mma.sync.aligned.m16n8k16.row.col.f32.f16.f16.f32 "
        "{%0,%1,%2,%3}, {%4,%5,%6,%7}, {%8,%9}, {%0,%1,%2,%3};"
        : "+f"(d[0]), "+f"(d[1]), "+f"(d[2]), "+f"(d[3])
        : "r"(a0), "r"(a1), "r"(a2), "r"(a3), "r"(b0), "r"(b1));
}
__device__ __forceinline__ void ldm_x4(uint32_t& r0, uint32_t& r1, uint32_t& r2,
                                       uint32_t& r3, uint32_t addr) {
    asm volatile("ldmatrix.sync.aligned.m8n8.x4.shared.b16 {%0,%1,%2,%3}, [%4];"
        : "=r"(r0), "=r"(r1), "=r"(r2), "=r"(r3) : "r"(addr));
}
__device__ __forceinline__ void ldm_x2(uint32_t& r0, uint32_t& r1, uint32_t addr) {
    asm volatile("ldmatrix.sync.aligned.m8n8.x2.shared.b16 {%0,%1}, [%2];"
        : "=r"(r0), "=r"(r1) : "r"(addr));
}
__device__ __forceinline__ float2 h2f2(unsigned v) {
    __half2 h = *reinterpret_cast<__half2*>(&v);
    return __half22float2(h);
}
// packed f32x2 FMA: acc += half2(hv)-as-float2 * wv2  (bit-identical to 2 scalar FMAs)
__device__ __forceinline__ void ffma2h(unsigned long long& acc, unsigned hv,
                                       unsigned long long wv2) {
    float2 c = h2f2(hv);
    unsigned long long cp;
    asm("mov.b64 %0, {%1,%2};" : "=l"(cp) : "f"(c.x), "f"(c.y));
    asm("fma.rn.f32x2 %0, %1, %2, %0;" : "+l"(acc) : "l"(cp), "l"(wv2));
}
__device__ __forceinline__ unsigned cvth2(unsigned long long a) {
    float lo, hi;
    asm("mov.b64 {%0,%1}, %2;" : "=f"(lo), "=f"(hi) : "l"(a));
    __half2 h = __floats2half2_rn(lo, hi);
    return *reinterpret_cast<unsigned*>(&h);
}

// ---------------- Kernel 1: fused prep (transpose + weight permute + bias)
// Transpose: 32p x 256c tiles, 32 LDGs in flight per thread, XOR-swizzled smem.
#define TPB 313   // ceil(10000/32)
__global__ void k_prep(const float* __restrict__ x,
                       const float* __restrict__ conv_w,
                       const float* __restrict__ conv_b) {
    int bid = blockIdx.x;
    int tid = threadIdx.x;
    if (bid < TPB*4) {
        __shared__ float tile[256][33];      // 33.8 KB
        int p0 = (bid % TPB) * 32;
        int c0 = (bid / TPB) * 256;
        int tx = tid & 31, ty = tid >> 5;    // ty 0..7
        int p = p0 + tx;
        bool pin = (p < FH*FW);
        #pragma unroll
        for (int j = 0; j < 32; j++) {
            int c = c0 + ty + j*8;           // rows ty+j*8 cover 0..255
            float v = 0.0f;
            if (pin) v = x[(size_t)c*(FH*FW) + p];
            tile[ty + j*8][tx ^ j] = v;      // swizzle col by (row>>3)=j
        }
        __syncthreads();
        #pragma unroll
        for (int i = 0; i < 4; i++) {
            int item = i*256 + tid;
            int pl = item >> 5;              // 0..31
            int cg = item & 31;              // 0..31 (8 ch each)
            int pw = p0 + pl;
            if (pw < FH*FW) {
                int sc = pl ^ cg;            // unswizzle: row>>3 = cg
                uint4 o;
                __half2 h;
                h = __floats2half2_rn(tile[cg*8+0][sc], tile[cg*8+1][sc]); o.x = *(unsigned*)&h;
                h = __floats2half2_rn(tile[cg*8+2][sc], tile[cg*8+3][sc]); o.y = *(unsigned*)&h;
                h = __floats2half2_rn(tile[cg*8+4][sc], tile[cg*8+5][sc]); o.z = *(unsigned*)&h;
                h = __floats2half2_rn(tile[cg*8+6][sc], tile[cg*8+7][sc]); o.w = *(unsigned*)&h;
                *(uint4*)&g_xt[(size_t)pw*NC + c0 + cg*8] = o;
            }
        }
    } else if (bid < TPB*4 + 276) {
        int idx = (bid - TPB*4)*256 + tid;
        if (idx >= NTP*NBINS*16) return;
        int t = idx / (NBINS*16);
        int rem = idx - t*(NBINS*16);
        int bin = rem >> 4;
        int c0 = (rem & 15) * 64;
        __half* dst = g_wp2 + (size_t)t*KTOT + bin*NC + c0;
        if (t < NT) {
            const float* src = conv_w + ((size_t)t*NBINS + bin)*NC + c0;
            #pragma unroll
            for (int j = 0; j < 64; j += 8) {
                float4 f0 = *(const float4*)(src + j);
                float4 f1 = *(const float4*)(src + j + 4);
                __half2 h0 = __floats2half2_rn(f0.x, f0.y);
                __half2 h1 = __floats2half2_rn(f0.z, f0.w);
                __half2 h2 = __floats2half2_rn(f1.x, f1.y);
                __half2 h3 = __floats2half2_rn(f1.z, f1.w);
                uint4 o;
                o.x = *reinterpret_cast<unsigned*>(&h0);
                o.y = *reinterpret_cast<unsigned*>(&h1);
                o.z = *reinterpret_cast<unsigned*>(&h2);
                o.w = *reinterpret_cast<unsigned*>(&h3);
                *reinterpret_cast<uint4*>(dst + j) = o;
            }
        } else {
            uint4 z = {0u, 0u, 0u, 0u};
            #pragma unroll
            for (int j = 0; j < 64; j += 8) *reinterpret_cast<uint4*>(dst + j) = z;
        }
    } else {
        if (tid < 96) {
            float bm = 0.0f;
            if (tid < NT) {
                #pragma unroll 7
                for (int b = 0; b < NBINS; b++) bm += conv_b[tid*NBINS + b];
                bm *= (1.0f/49.0f);
            }
            g_bias[tid] = bm;
        }
    }
}

// ---------------- Kernel 2: FUSED PSROIAlign pooling + HMMA GEMM
// grid (NBINS, 16), 256 threads, 2 CTAs/SM. CTA: bin b, regions [mt*64, +64).
// Warp map: rbg = w&1 (32 rows), ng = w>>1 (n-tile group of 3/3/3/2).
__global__ void __launch_bounds__(256, 2) k_poolmma(const float* __restrict__ regions) {
    extern __shared__ char dsm[];
    char* Ab = dsm;
    char* Bb = dsm + BB_OFF;
    uint2* smeta = (uint2*)(dsm + MP_OFF);

    uint32_t su;
    asm("{ .reg .u64 t; cvta.to.shared.u64 t, %1; cvt.u32.u64 %0, t; }" : "=r"(su) : "l"(dsm));

    int tid = threadIdx.x;
    int w = tid >> 5, l = tid & 31;
    int b = blockIdx.x, mt = blockIdx.y;
    int m0 = mt * MTILE;
    int u = b / NK, v = b - u*NK;

    // ---- meta: 16 (pixel byte-offset, weight) pairs per region ----
    if (tid < MTILE) {
        float4 reg = reinterpret_cast<const float4*>(regions)[m0 + tid];
        float top  = (reg.x - reg.z*0.5f)*(float)FH;
        float left = (reg.y - reg.w*0.5f)*(float)FW;
        float bh = reg.z*((float)FH/(float)NK);
        float bw = reg.w*((float)FW/(float)NK);
        int yi[2][2]; float wy[2][2];
        int xi[2][2]; float wx[2][2];
        #pragma unroll
        for (int s = 0; s < 2; s++) {
            float ys = top + ((float)u + (s ? 0.75f : 0.25f))*bh;
            ys = fminf(fmaxf(ys, 0.0f), 99.0f);
            float yf = floorf(ys);
            int y0 = (int)yf;
            yi[s][0] = y0; yi[s][1] = min(y0 + 1, 99);
            wy[s][1] = ys - yf; wy[s][0] = 1.0f - wy[s][1];
            float xs = left + ((float)v + (s ? 0.75f : 0.25f))*bw;
            xs = fminf(fmaxf(xs, 0.0f), 99.0f);
            float xf = floorf(xs);
            int x0 = (int)xf;
            xi[s][0] = x0; xi[s][1] = min(x0 + 1, 99);
            wx[s][1] = xs - xf; wx[s][0] = 1.0f - wx[s][1];
        }
        #pragma unroll
        for (int sy = 0; sy < 2; sy++)
        #pragma unroll
        for (int sx = 0; sx < 2; sx++)
        #pragma unroll
        for (int cy = 0; cy < 2; cy++)
        #pragma unroll
        for (int cx = 0; cx < 2; cx++) {
            int i = sy*8 + sx*4 + cy*2 + cx;
            uint32_t pix = (uint32_t)(yi[sy][cy]*FW + xi[sx][cx]);
            uint2 m;
            m.x = pix * (NC*2);            // byte offset into g_xt
            m.y = __float_as_uint(wy[sy][cy]*wx[sx][cx]);
            smeta[tid*16 + i] = m;
        }
    }

    // ---- B prologue: chunk 0 into stage 0 ----
    const char* gB = (const char*)g_wp2 + (size_t)b*NC*2;
    #pragma unroll
    for (int i = 0; i < 6; i++) {
        int ch = i*256 + tid;
        if (ch < NTP*16) {
            int row = ch >> 4, c16 = ch & 15;
            cpa16(Bb + row*ROWB + c16*16, gB + (size_t)row*(KTOT*2) + c16*16);
        }
    }
    cpa_commit();
    __syncthreads();   // meta visible

    int rbg = w & 1;          // 32-row group
    int ng = w >> 1;          // n-tile group: [ng*3, +3), last group 2
    int t0 = ng*3;
    int tcnt = (ng == 3) ? 2 : 3;

    float acc[2][3][4];
    #pragma unroll
    for (int h = 0; h < 2; h++)
        #pragma unroll
        for (int t = 0; t < 3; t++)
            #pragma unroll
            for (int i = 0; i < 4; i++) acc[h][t][i] = 0.0f;

    int r8 = tid >> 3;        // region group 0..31 (task adds +32)
    int lane8 = tid & 7;      // 16B lane within each 128B half

    const char* xbase = (const char*)g_xt + lane8*16;

    // ldmatrix per-lane address offsets (bytes)
    int lm = l >> 3;
    int lr = l & 7;
    uint32_t aOff0 = (uint32_t)((rbg*32 + (lm & 1)*8 + lr)*ROWB + (lm >> 1)*16);
    uint32_t aOff1 = aOff0 + 16*ROWB;
    uint32_t bOff4 = (uint32_t)(((lm >> 1)*8 + lr)*ROWB + (lm & 1)*16 + t0*8*ROWB);
    uint32_t bOff2 = (uint32_t)((l & 7)*ROWB + ((l >> 3) & 1)*16 + (t0+2)*8*ROWB);

    int bStage = 0;           // stage holding chunk kc
    for (int kc = 0; kc < NCH; kc++) {
        int sA = kc & 1;
        uint32_t kb = (uint32_t)kc * 256;

        // ---- gather: 2 tasks, 8 lanes/region, 2x128B per sample, f32x2 FMAs ----
        #pragma unroll
        for (int task = 0; task < 2; task++) {
            int rr = r8 + task*32;
            const uint2* mp = smeta + rr*16;
            unsigned long long f[8];
            #pragma unroll
            for (int j = 0; j < 8; j++) f[j] = 0ull;
            #pragma unroll
            for (int i = 0; i < 16; i++) {
                uint2 m = mp[i];
                uint32_t off = m.x + kb;
                float wv = __uint_as_float(m.y);
                unsigned long long wv2;
                asm("mov.b64 %0, {%1,%1};" : "=l"(wv2) : "f"(wv));
                uint4 d0 = *(const uint4*)(xbase + off);
                uint4 d1 = *(const uint4*)(xbase + off + 128);
                ffma2h(f[0], d0.x, wv2);
                ffma2h(f[1], d0.y, wv2);
                ffma2h(f[2], d0.z, wv2);
                ffma2h(f[3], d0.w, wv2);
                ffma2h(f[4], d1.x, wv2);
                ffma2h(f[5], d1.y, wv2);
                ffma2h(f[6], d1.z, wv2);
                ffma2h(f[7], d1.w, wv2);
            }
            uint4 o0, o1;
            o0.x = cvth2(f[0]); o0.y = cvth2(f[1]);
            o0.z = cvth2(f[2]); o0.w = cvth2(f[3]);
            o1.x = cvth2(f[4]); o1.y = cvth2(f[5]);
            o1.z = cvth2(f[6]); o1.w = cvth2(f[7]);
            char* arow = Ab + sA*AB_SZ + rr*ROWB + lane8*16;
            *(uint4*)(arow) = o0;
            *(uint4*)(arow + 128) = o1;
        }

        // ---- prefetch B[kc+1] into stage (kc+1)%3 ----
        if (kc + 1 < NCH) {
            int st = bStage + 1; if (st == 3) st = 0;
            #pragma unroll
            for (int i = 0; i < 6; i++) {
                int ch = i*256 + tid;
                if (ch < NTP*16) {
                    int row = ch >> 4, c16 = ch & 15;
                    cpa16(Bb + st*BB_SZ + row*ROWB + c16*16,
                          gB + (size_t)row*(KTOT*2) + (kc+1)*256 + c16*16);
                }
            }
        }
        cpa_commit();
        cpa_wait<1>();      // B[kc] complete (this thread's share)
        __syncthreads();    // all shares + A stores visible

        // ---- MMA over this 128-K chunk ----
        uint32_t aBase0 = su + sA*AB_SZ + aOff0;
        uint32_t aBase1 = su + sA*AB_SZ + aOff1;
        uint32_t bBase = su + BB_OFF + bStage*BB_SZ;
        #pragma unroll
        for (int q = 0; q < 8; q++) {
            uint32_t k0b = (uint32_t)(q*32);
            uint32_t aA0, aA1, aA2, aA3, aB0, aB1, aB2, aB3;
            ldm_x4(aA0, aA1, aA2, aA3, aBase0 + k0b);
            ldm_x4(aB0, aB1, aB2, aB3, aBase1 + k0b);
            if (ng < 3) {
                uint32_t b0, b1, b2, b3, b4, b5;
                ldm_x4(b0, b1, b2, b3, bBase + bOff4 + k0b);
                ldm_x2(b4, b5, bBase + bOff2 + k0b);
                mma16816(acc[0][0], aA0, aA1, aA2, aA3, b0, b1);
                mma16816(acc[0][1], aA0, aA1, aA2, aA3, b2, b3);
                mma16816(acc[0][2], aA0, aA1, aA2, aA3, b4, b5);
                mma16816(acc[1][0], aB0, aB1, aB2, aB3, b0, b1);
                mma16816(acc[1][1], aB0, aB1, aB2, aB3, b2, b3);
                mma16816(acc[1][2], aB0, aB1, aB2, aB3, b4, b5);
            } else {
                uint32_t b0, b1, b2, b3;
                ldm_x4(b0, b1, b2, b3, bBase + bOff4 + k0b);
                mma16816(acc[0][0], aA0, aA1, aA2, aA3, b0, b1);
                mma16816(acc[0][1], aA0, aA1, aA2, aA3, b2, b3);
                mma16816(acc[1][0], aB0, aB1, aB2, aB3, b0, b1);
                mma16816(acc[1][1], aB0, aB1, aB2, aB3, b2, b3);
            }
        }
        bStage++; if (bStage == 3) bStage = 0;
    }

    // ---- epilogue: write (r, bin, t) layout ----
    int mr = l >> 2;
    int kc2 = (l & 3) * 2;
    #pragma unroll
    for (int h = 0; h < 2; h++) {
        int r0 = m0 + rbg*32 + h*16 + mr;
        #pragma unroll
        for (int t = 0; t < 3; t++) {
            if (t < tcnt) {
                int c = (t0 + t)*8 + kc2;
                *(float2*)&g_partial[((size_t)r0*NBINS + b)*NTP + c] =
                    make_float2(acc[h][t][0], acc[h][t][1]);
                *(float2*)&g_partial[((size_t)(r0+8)*NBINS + b)*NTP + c] =
                    make_float2(acc[h][t][2], acc[h][t][3]);
            }
        }
    }
}

// ---------------- Kernel 3: reduce bins (float4), apply 1/196 mean + bias
__global__ void k_reduce(float* __restrict__ out) {
    int tx = threadIdx.x;
    int r = blockIdx.x*8 + threadIdx.y;
    if (tx >= 22) return;
    const float4* po = (const float4*)(g_partial + (size_t)r*NBINS*NTP) + tx;
    float4 a = make_float4(0.f, 0.f, 0.f, 0.f);
    #pragma unroll
    for (int b = 0; b < NBINS; b++) {
        float4 v = po[b*(NTP/4)];
        a.x += v.x; a.y += v.y; a.z += v.z; a.w += v.w;
    }
    int t = tx*4;
    float s = 1.0f/196.0f;
    float vs[4] = {a.x*s, a.y*s, a.z*s, a.w*s};
    #pragma unroll
    for (int i = 0; i < 4; i++) {
        int ti = t + i;
        if (ti < NT) out[r*NT + ti] = vs[i] + g_bias[ti];
    }
}

extern "C" void kernel_launch(void* const* d_in, const int* in_sizes, int n_in,
                              void* d_out, int out_size) {
    const float* x       = (const float*)d_in[0];   // (1024, 100, 100)
    const float* regions = (const float*)d_in[1];   // (1024, 4)
    const float* conv_w  = (const float*)d_in[2];   // (3969, 1024)
    const float* conv_b  = (const float*)d_in[3];   // (3969,)
    float* out = (float*)d_out;                     // (1024, 81)

    cudaFuncSetAttribute(k_poolmma, cudaFuncAttributeMaxDynamicSharedMemorySize, SM_TOTAL);

    k_prep<<<TPB*4 + 276 + 1, 256>>>(x, conv_w, conv_b);
    k_poolmma<<<dim3(NBINS, NR/MTILE), 256, SM_TOTAL>>>(regions);
    k_reduce<<<NR/8, dim3(32, 8)>>>(out);
}

// round 17
// speedup vs baseline: 1.0715x; 1.0100x over previous
#include <cuda_runtime.h>
#include <cuda_fp16.h>
#include <cstdint>

// Problem constants
#define FH 100
#define FW 100
#define NC 1024
#define NK 7
#define NT 81
#define NTP 88           // padded targets (11 n8-tiles; rows 81..87 zero)
#define NR 1024
#define NBINS 49
#define KTOT (NBINS*NC)  // 50176

// Fused kernel tiling: grid (NBINS, 16, 2). CTA: 1 bin, 64 regions, 4 chunks of 128 ch.
#define MTILE 64
#define NCHC 4           // chunks per CTA (of 8 total; z selects half)

// SMEM layout (rows are 256B data + 16B pad = 272B, ldmatrix conflict-free)
#define ROWB 272
#define AB_SZ    (MTILE*ROWB)            // 17408, x2 stages
#define BB_SZ    (NTP*ROWB)              // 23936, x3 stages
#define BB_OFF   (2*AB_SZ)               // 34816
#define MP_OFF   (BB_OFF + 3*BB_SZ)      // 106624: meta uint2 [64][16]
#define SM_TOTAL (MP_OFF + MTILE*16*8)   // 114816

// Scratch (device globals; no allocation)
__device__ __half g_xt[FH*FW*NC];                        // (HW, C) fp16
__device__ __half g_wp2[(size_t)NTP*KTOT];               // (Tpad, bin*C) fp16, K-major
__device__ float  g_partial[(size_t)NR*NBINS*2*NTP];     // (r, bin*2+z, t) f32
__device__ float  g_bias[96];

// ---------------- helpers ----------------
__device__ __forceinline__ void cpa16(void* s, const void* g) {
    uint32_t a;
    asm("{ .reg .u64 t; cvta.to.shared.u64 t, %1; cvt.u32.u64 %0, t; }" : "=r"(a) : "l"(s));
    asm volatile("cp.async.cg.shared.global [%0], [%1], 16;" :: "r"(a), "l"(g));
}
__device__ __forceinline__ void cpa_commit() { asm volatile("cp.async.commit_group;"); }
template<int N> __device__ __forceinline__ void cpa_wait() {
    asm volatile("cp.async.wait_group %0;" :: "n"(N));
}
__device__ __forceinline__ void mma16816(float* d, uint32_t a0, uint32_t a1,
                                         uint32_t a2, uint32_t a3,
                                         uint32_t b0, uint32_t b1) {
    asm volatile(
        "mma.sync.aligned.m16n8k16.row.col.f32.f16.f16.f32 "
        "{%0,%1,%2,%3}, {%4,%5,%6,%7}, {%8,%9}, {%0,%1,%2,%3};"
        : "+f"(d[0]), "+f"(d[1]), "+f"(d[2]), "+f"(d[3])
        : "r"(a0), "r"(a1), "r"(a2), "r"(a3), "r"(b0), "r"(b1));
}
__device__ __forceinline__ void ldm_x4(uint32_t& r0, uint32_t& r1, uint32_t& r2,
                                       uint32_t& r3, uint32_t addr) {
    asm volatile("ldmatrix.sync.aligned.m8n8.x4.shared.b16 {%0,%1,%2,%3}, [%4];"
        : "=r"(r0), "=r"(r1), "=r"(r2), "=r"(r3) : "r"(addr));
}
__device__ __forceinline__ void ldm_x2(uint32_t& r0, uint32_t& r1, uint32_t addr) {
    asm volatile("ldmatrix.sync.aligned.m8n8.x2.shared.b16 {%0,%1}, [%2];"
        : "=r"(r0), "=r"(r1) : "r"(addr));
}
__device__ __forceinline__ float2 h2f2(unsigned v) {
    __half2 h = *reinterpret_cast<__half2*>(&v);
    return __half22float2(h);
}
// packed f32x2 FMA: acc += half2(hv)-as-float2 * wv2  (bit-identical to 2 scalar FMAs)
__device__ __forceinline__ void ffma2h(unsigned long long& acc, unsigned hv,
                                       unsigned long long wv2) {
    float2 c = h2f2(hv);
    unsigned long long cp;
    asm("mov.b64 %0, {%1,%2};" : "=l"(cp) : "f"(c.x), "f"(c.y));
    asm("fma.rn.f32x2 %0, %1, %2, %0;" : "+l"(acc) : "l"(cp), "l"(wv2));
}
__device__ __forceinline__ unsigned cvth2(unsigned long long a) {
    float lo, hi;
    asm("mov.b64 {%0,%1}, %2;" : "=f"(lo), "=f"(hi) : "l"(a));
    __half2 h = __floats2half2_rn(lo, hi);
    return *reinterpret_cast<unsigned*>(&h);
}

// ---------------- Kernel 1: fused prep (transpose + weight permute + bias)
// Transpose: 32p x 256c tiles, 32 LDGs in flight per thread, XOR-swizzled smem.
#define TPB 313   // ceil(10000/32)
__global__ void k_prep(const float* __restrict__ x,
                       const float* __restrict__ conv_w,
                       const float* __restrict__ conv_b) {
    int bid = blockIdx.x;
    int tid = threadIdx.x;
    if (bid < TPB*4) {
        __shared__ float tile[256][33];      // 33.8 KB
        int p0 = (bid % TPB) * 32;
        int c0 = (bid / TPB) * 256;
        int tx = tid & 31, ty = tid >> 5;    // ty 0..7
        int p = p0 + tx;
        bool pin = (p < FH*FW);
        #pragma unroll
        for (int j = 0; j < 32; j++) {
            int c = c0 + ty + j*8;           // rows ty+j*8 cover 0..255
            float v = 0.0f;
            if (pin) v = x[(size_t)c*(FH*FW) + p];
            tile[ty + j*8][tx ^ j] = v;      // swizzle col by (row>>3)=j
        }
        __syncthreads();
        #pragma unroll
        for (int i = 0; i < 4; i++) {
            int item = i*256 + tid;
            int pl = item >> 5;              // 0..31
            int cg = item & 31;              // 0..31 (8 ch each)
            int pw = p0 + pl;
            if (pw < FH*FW) {
                int sc = pl ^ cg;            // unswizzle: row>>3 = cg
                uint4 o;
                __half2 h;
                h = __floats2half2_rn(tile[cg*8+0][sc], tile[cg*8+1][sc]); o.x = *(unsigned*)&h;
                h = __floats2half2_rn(tile[cg*8+2][sc], tile[cg*8+3][sc]); o.y = *(unsigned*)&h;
                h = __floats2half2_rn(tile[cg*8+4][sc], tile[cg*8+5][sc]); o.z = *(unsigned*)&h;
                h = __floats2half2_rn(tile[cg*8+6][sc], tile[cg*8+7][sc]); o.w = *(unsigned*)&h;
                *(uint4*)&g_xt[(size_t)pw*NC + c0 + cg*8] = o;
            }
        }
    } else if (bid < TPB*4 + 276) {
        int idx = (bid - TPB*4)*256 + tid;
        if (idx >= NTP*NBINS*16) return;
        int t = idx / (NBINS*16);
        int rem = idx - t*(NBINS*16);
        int bin = rem >> 4;
        int c0 = (rem & 15) * 64;
        __half* dst = g_wp2 + (size_t)t*KTOT + bin*NC + c0;
        if (t < NT) {
            const float* src = conv_w + ((size_t)t*NBINS + bin)*NC + c0;
            #pragma unroll
            for (int j = 0; j < 64; j += 8) {
                float4 f0 = *(const float4*)(src + j);
                float4 f1 = *(const float4*)(src + j + 4);
                __half2 h0 = __floats2half2_rn(f0.x, f0.y);
                __half2 h1 = __floats2half2_rn(f0.z, f0.w);
                __half2 h2 = __floats2half2_rn(f1.x, f1.y);
                __half2 h3 = __floats2half2_rn(f1.z, f1.w);
                uint4 o;
                o.x = *reinterpret_cast<unsigned*>(&h0);
                o.y = *reinterpret_cast<unsigned*>(&h1);
                o.z = *reinterpret_cast<unsigned*>(&h2);
                o.w = *reinterpret_cast<unsigned*>(&h3);
                *reinterpret_cast<uint4*>(dst + j) = o;
            }
        } else {
            uint4 z = {0u, 0u, 0u, 0u};
            #pragma unroll
            for (int j = 0; j < 64; j += 8) *reinterpret_cast<uint4*>(dst + j) = z;
        }
    } else {
        if (tid < 96) {
            float bm = 0.0f;
            if (tid < NT) {
                #pragma unroll 7
                for (int b = 0; b < NBINS; b++) bm += conv_b[tid*NBINS + b];
                bm *= (1.0f/49.0f);
            }
            g_bias[tid] = bm;
        }
    }
}

// ---------------- Kernel 2: FUSED PSROIAlign pooling + HMMA GEMM (K-split x2)
// grid (NBINS, 16, 2), 256 threads, 2 CTAs/SM. CTA: bin b, regions [mt*64, +64),
// K-chunks [z*4, z*4+4). Warp map: rbg = w&1 (32 rows), ng = w>>1.
__global__ void __launch_bounds__(256, 2) k_poolmma(const float* __restrict__ regions) {
    extern __shared__ char dsm[];
    char* Ab = dsm;
    char* Bb = dsm + BB_OFF;
    uint2* smeta = (uint2*)(dsm + MP_OFF);

    uint32_t su;
    asm("{ .reg .u64 t; cvta.to.shared.u64 t, %1; cvt.u32.u64 %0, t; }" : "=r"(su) : "l"(dsm));

    int tid = threadIdx.x;
    int w = tid >> 5, l = tid & 31;
    int b = blockIdx.x, mt = blockIdx.y;
    int z = blockIdx.z;
    int kc0 = z * NCHC;
    int m0 = mt * MTILE;
    int u = b / NK, v = b - u*NK;

    // ---- meta: 16 (pixel byte-offset, weight) pairs per region ----
    if (tid < MTILE) {
        float4 reg = reinterpret_cast<const float4*>(regions)[m0 + tid];
        float top  = (reg.x - reg.z*0.5f)*(float)FH;
        float left = (reg.y - reg.w*0.5f)*(float)FW;
        float bh = reg.z*((float)FH/(float)NK);
        float bw = reg.w*((float)FW/(float)NK);
        int yi[2][2]; float wy[2][2];
        int xi[2][2]; float wx[2][2];
        #pragma unroll
        for (int s = 0; s < 2; s++) {
            float ys = top + ((float)u + (s ? 0.75f : 0.25f))*bh;
            ys = fminf(fmaxf(ys, 0.0f), 99.0f);
            float yf = floorf(ys);
            int y0 = (int)yf;
            yi[s][0] = y0; yi[s][1] = min(y0 + 1, 99);
            wy[s][1] = ys - yf; wy[s][0] = 1.0f - wy[s][1];
            float xs = left + ((float)v + (s ? 0.75f : 0.25f))*bw;
            xs = fminf(fmaxf(xs, 0.0f), 99.0f);
            float xf = floorf(xs);
            int x0 = (int)xf;
            xi[s][0] = x0; xi[s][1] = min(x0 + 1, 99);
            wx[s][1] = xs - xf; wx[s][0] = 1.0f - wx[s][1];
        }
        #pragma unroll
        for (int sy = 0; sy < 2; sy++)
        #pragma unroll
        for (int sx = 0; sx < 2; sx++)
        #pragma unroll
        for (int cy = 0; cy < 2; cy++)
        #pragma unroll
        for (int cx = 0; cx < 2; cx++) {
            int i = sy*8 + sx*4 + cy*2 + cx;
            uint32_t pix = (uint32_t)(yi[sy][cy]*FW + xi[sx][cx]);
            uint2 m;
            m.x = pix * (NC*2);            // byte offset into g_xt
            m.y = __float_as_uint(wy[sy][cy]*wx[sx][cx]);
            smeta[tid*16 + i] = m;
        }
    }

    // ---- B prologue: chunk kc0 into stage 0 ----
    const char* gB = (const char*)g_wp2 + (size_t)b*NC*2;
    #pragma unroll
    for (int i = 0; i < 6; i++) {
        int ch = i*256 + tid;
        if (ch < NTP*16) {
            int row = ch >> 4, c16 = ch & 15;
            cpa16(Bb + row*ROWB + c16*16,
                  gB + (size_t)row*(KTOT*2) + kc0*256 + c16*16);
        }
    }
    cpa_commit();
    __syncthreads();   // meta visible

    int rbg = w & 1;          // 32-row group
    int ng = w >> 1;          // n-tile group: [ng*3, +3), last group 2
    int t0 = ng*3;
    int tcnt = (ng == 3) ? 2 : 3;

    float acc[2][3][4];
    #pragma unroll
    for (int h = 0; h < 2; h++)
        #pragma unroll
        for (int t = 0; t < 3; t++)
            #pragma unroll
            for (int i = 0; i < 4; i++) acc[h][t][i] = 0.0f;

    int r8 = tid >> 3;        // region group 0..31 (task adds +32)
    int lane8 = tid & 7;      // 16B lane within each 128B half

    const char* xbase = (const char*)g_xt + lane8*16;

    // ldmatrix per-lane address offsets (bytes)
    int lm = l >> 3;
    int lr = l & 7;
    uint32_t aOff0 = (uint32_t)((rbg*32 + (lm & 1)*8 + lr)*ROWB + (lm >> 1)*16);
    uint32_t aOff1 = aOff0 + 16*ROWB;
    uint32_t bOff4 = (uint32_t)(((lm >> 1)*8 + lr)*ROWB + (lm & 1)*16 + t0*8*ROWB);
    uint32_t bOff2 = (uint32_t)((l & 7)*ROWB + ((l >> 3) & 1)*16 + (t0+2)*8*ROWB);

    int bStage = 0;           // stage holding chunk j
    for (int j = 0; j < NCHC; j++) {
        int sA = j & 1;
        uint32_t kb = (uint32_t)(kc0 + j) * 256;

        // ---- gather: 2 tasks, 8 lanes/region, 2x128B per sample, f32x2 FMAs ----
        #pragma unroll
        for (int task = 0; task < 2; task++) {
            int rr = r8 + task*32;
            const uint2* mp = smeta + rr*16;
            unsigned long long f[8];
            #pragma unroll
            for (int q = 0; q < 8; q++) f[q] = 0ull;
            #pragma unroll
            for (int i = 0; i < 16; i++) {
                uint2 m = mp[i];
                uint32_t off = m.x + kb;
                float wv = __uint_as_float(m.y);
                unsigned long long wv2;
                asm("mov.b64 %0, {%1,%1};" : "=l"(wv2) : "f"(wv));
                uint4 d0 = *(const uint4*)(xbase + off);
                uint4 d1 = *(const uint4*)(xbase + off + 128);
                ffma2h(f[0], d0.x, wv2);
                ffma2h(f[1], d0.y, wv2);
                ffma2h(f[2], d0.z, wv2);
                ffma2h(f[3], d0.w, wv2);
                ffma2h(f[4], d1.x, wv2);
                ffma2h(f[5], d1.y, wv2);
                ffma2h(f[6], d1.z, wv2);
                ffma2h(f[7], d1.w, wv2);
            }
            uint4 o0, o1;
            o0.x = cvth2(f[0]); o0.y = cvth2(f[1]);
            o0.z = cvth2(f[2]); o0.w = cvth2(f[3]);
            o1.x = cvth2(f[4]); o1.y = cvth2(f[5]);
            o1.z = cvth2(f[6]); o1.w = cvth2(f[7]);
            char* arow = Ab + sA*AB_SZ + rr*ROWB + lane8*16;
            *(uint4*)(arow) = o0;
            *(uint4*)(arow + 128) = o1;
        }

        // ---- prefetch B[j+1] into stage (j+1)%3 ----
        if (j + 1 < NCHC) {
            int st = bStage + 1; if (st == 3) st = 0;
            #pragma unroll
            for (int i = 0; i < 6; i++) {
                int ch = i*256 + tid;
                if (ch < NTP*16) {
                    int row = ch >> 4, c16 = ch & 15;
                    cpa16(Bb + st*BB_SZ + row*ROWB + c16*16,
                          gB + (size_t)row*(KTOT*2) + (kc0 + j + 1)*256 + c16*16);
                }
            }
        }
        cpa_commit();
        cpa_wait<1>();      // B[j] complete (this thread's share)
        __syncthreads();    // all shares + A stores visible

        // ---- MMA over this 128-K chunk ----
        uint32_t aBase0 = su + sA*AB_SZ + aOff0;
        uint32_t aBase1 = su + sA*AB_SZ + aOff1;
        uint32_t bBase = su + BB_OFF + bStage*BB_SZ;
        #pragma unroll
        for (int q = 0; q < 8; q++) {
            uint32_t k0b = (uint32_t)(q*32);
            uint32_t aA0, aA1, aA2, aA3, aB0, aB1, aB2, aB3;
            ldm_x4(aA0, aA1, aA2, aA3, aBase0 + k0b);
            ldm_x4(aB0, aB1, aB2, aB3, aBase1 + k0b);
            if (ng < 3) {
                uint32_t b0, b1, b2, b3, b4, b5;
                ldm_x4(b0, b1, b2, b3, bBase + bOff4 + k0b);
                ldm_x2(b4, b5, bBase + bOff2 + k0b);
                mma16816(acc[0][0], aA0, aA1, aA2, aA3, b0, b1);
                mma16816(acc[0][1], aA0, aA1, aA2, aA3, b2, b3);
                mma16816(acc[0][2], aA0, aA1, aA2, aA3, b4, b5);
                mma16816(acc[1][0], aB0, aB1, aB2, aB3, b0, b1);
                mma16816(acc[1][1], aB0, aB1, aB2, aB3, b2, b3);
                mma16816(acc[1][2], aB0, aB1, aB2, aB3, b4, b5);
            } else {
                uint32_t b0, b1, b2, b3;
                ldm_x4(b0, b1, b2, b3, bBase + bOff4 + k0b);
                mma16816(acc[0][0], aA0, aA1, aA2, aA3, b0, b1);
                mma16816(acc[0][1], aA0, aA1, aA2, aA3, b2, b3);
                mma16816(acc[1][0], aB0, aB1, aB2, aB3, b0, b1);
                mma16816(acc[1][1], aB0, aB1, aB2, aB3, b2, b3);
            }
        }
        bStage++; if (bStage == 3) bStage = 0;
    }

    // ---- epilogue: write (r, bin*2+z, t) layout ----
    int mr = l >> 2;
    int kc2 = (l & 3) * 2;
    #pragma unroll
    for (int h = 0; h < 2; h++) {
        int r0 = m0 + rbg*32 + h*16 + mr;
        #pragma unroll
        for (int t = 0; t < 3; t++) {
            if (t < tcnt) {
                int c = (t0 + t)*8 + kc2;
                size_t base0 = ((size_t)r0*(NBINS*2) + b*2 + z)*NTP + c;
                size_t base1 = ((size_t)(r0+8)*(NBINS*2) + b*2 + z)*NTP + c;
                *(float2*)&g_partial[base0] = make_float2(acc[h][t][0], acc[h][t][1]);
                *(float2*)&g_partial[base1] = make_float2(acc[h][t][2], acc[h][t][3]);
            }
        }
    }
}

// ---------------- Kernel 3: reduce 98 partials (float4), apply 1/196 mean + bias
__global__ void k_reduce(float* __restrict__ out) {
    int tx = threadIdx.x;
    int r = blockIdx.x*8 + threadIdx.y;
    if (tx >= 22) return;
    const float4* po = (const float4*)(g_partial + (size_t)r*(NBINS*2)*NTP) + tx;
    float4 a = make_float4(0.f, 0.f, 0.f, 0.f);
    #pragma unroll
    for (int b = 0; b < NBINS*2; b++) {
        float4 v = po[b*(NTP/4)];
        a.x += v.x; a.y += v.y; a.z += v.z; a.w += v.w;
    }
    int t = tx*4;
    float s = 1.0f/196.0f;
    float vs[4] = {a.x*s, a.y*s, a.z*s, a.w*s};
    #pragma unroll
    for (int i = 0; i < 4; i++) {
        int ti = t + i;
        if (ti < NT) out[r*NT + ti] = vs[i] + g_bias[ti];
    }
}

extern "C" void kernel_launch(void* const* d_in, const int* in_sizes, int n_in,
                              void* d_out, int out_size) {
    const float* x       = (const float*)d_in[0];   // (1024, 100, 100)
    const float* regions = (const float*)d_in[1];   // (1024, 4)
    const float* conv_w  = (const float*)d_in[2];   // (3969, 1024)
    const float* conv_b  = (const float*)d_in[3];   // (3969,)
    float* out = (float*)d_out;                     // (1024, 81)

    cudaFuncSetAttribute(k_poolmma, cudaFuncAttributeMaxDynamicSharedMemorySize, SM_TOTAL);

    k_prep<<<TPB*4 + 276 + 1, 256>>>(x, conv_w, conv_b);
    k_poolmma<<<dim3(NBINS, NR/MTILE, 2), 256, SM_TOTAL>>>(regions);
    k_reduce<<<NR/8, dim3(32, 8)>>>(out);
}